// round 1
// baseline (speedup 1.0000x reference)
#include <cuda_runtime.h>

// Backflow fused kernel. One CTA per batch element.
// B=512, N=32 electrons, D=256 features, K=8 nuclei.
// elec MLP: 256->40->6->1 (ssp, ssp, linear)
// nuc  MLP: 256->81->25->8 (ssp, ssp, linear)

#define NTHREADS 512
#define NWARPS   16

// ---- shared memory layout (floats) ----
constexpr int OFF_XT   = 0;            // X transposed, padded: [256][33]
constexpr int OFF_W1   = 8448;         // ew1 [256][40]
constexpr int OFF_EB1  = 18688;        // 40
constexpr int OFF_W2   = 18728;        // ew2 [40][6]
constexpr int OFF_EB2  = 18968;        // 6
constexpr int OFF_W3   = 18974;        // ew3 [6]
constexpr int OFF_EB3  = 18980;        // 1
constexpr int OFF_NW1  = 18984;        // nw1 [256][81]
constexpr int OFF_NB1  = 39720;        // 81
constexpr int OFF_NW2  = 39804;        // nw2 [81][25]
constexpr int OFF_NB2  = 41829;        // 25
constexpr int OFF_NW3  = 41856;        // nw3 [25][8]
constexpr int OFF_NB3  = 42056;        // 8
constexpr int OFF_H1N  = 42064;        // nuc hidden1 [32][81]
constexpr int OFF_H2N  = 44656;        // nuc hidden2 [32][25]
constexpr int OFF_WN   = 45456;        // w_nuc [32][8]
constexpr int OFF_RS   = 45712;        // rs[b] [32][3]
constexpr int OFF_CRD  = 45808;        // coords [8][3]
constexpr int OFF_BFN  = 45832;        // bf_nuc [32][3]
constexpr int OFF_CUT  = 45928;        // cutoff [32]
constexpr int SMEM_FLOATS = 45960;
constexpr int SMEM_BYTES  = SMEM_FLOATS * 4;   // 183840 B

__device__ __forceinline__ float ssp(float x) {
    // softplus(x) - ln(2), numerically stable
    return fmaxf(x, 0.0f) + log1pf(__expf(-fabsf(x))) - 0.69314718055994530942f;
}

__device__ __forceinline__ void scopy(float* dst, const float* src, int n, int tid) {
    for (int t = tid; t < n; t += NTHREADS) dst[t] = src[t];
}

// Epilogue for one electron i: layers 2/3 of pair MLP + reduction + output write.
__device__ __forceinline__ void pair_epilogue(
    const float* __restrict__ acc, int i, int lane, const float* __restrict__ sm,
    float* __restrict__ out, int b)
{
    float h2[6];
    #pragma unroll
    for (int c = 0; c < 6; ++c) h2[c] = sm[OFF_EB2 + c];
    #pragma unroll
    for (int f = 0; f < 40; ++f) {
        float h = ssp(acc[f] + sm[OFF_EB1 + f]);
        #pragma unroll
        for (int c = 0; c < 6; ++c) h2[c] += h * sm[OFF_W2 + f * 6 + c];
    }
    float w = sm[OFF_EB3];
    #pragma unroll
    for (int c = 0; c < 6; ++c) w += ssp(h2[c]) * sm[OFF_W3 + c];

    float rix = sm[OFF_RS + i * 3 + 0];
    float riy = sm[OFF_RS + i * 3 + 1];
    float riz = sm[OFF_RS + i * 3 + 2];
    float dx = rix - sm[OFF_RS + lane * 3 + 0];
    float dy = riy - sm[OFF_RS + lane * 3 + 1];
    float dz = riz - sm[OFF_RS + lane * 3 + 2];
    if (lane == i) w = 0.0f;    // (diff is zero anyway; explicit for clarity)

    float cx = w * dx, cy = w * dy, cz = w * dz;
    #pragma unroll
    for (int off = 16; off; off >>= 1) {
        cx += __shfl_down_sync(0xffffffffu, cx, off);
        cy += __shfl_down_sync(0xffffffffu, cy, off);
        cz += __shfl_down_sync(0xffffffffu, cz, off);
    }
    if (lane == 0) {
        float s  = 1e-4f * sm[OFF_CUT + i];
        float bx = cx + sm[OFF_BFN + i * 3 + 0];
        float by = cy + sm[OFF_BFN + i * 3 + 1];
        float bz = cz + sm[OFF_BFN + i * 3 + 2];
        out[b * 96 + i * 3 + 0] = rix + s * bx;
        out[b * 96 + i * 3 + 1] = riy + s * by;
        out[b * 96 + i * 3 + 2] = riz + s * bz;
    }
}

__global__ __launch_bounds__(NTHREADS, 1)
void backflow_kernel(
    const float* __restrict__ rs, const float* __restrict__ xs, const float* __restrict__ coords,
    const float* __restrict__ ew1, const float* __restrict__ eb1,
    const float* __restrict__ ew2, const float* __restrict__ eb2,
    const float* __restrict__ ew3, const float* __restrict__ eb3,
    const float* __restrict__ nw1, const float* __restrict__ nb1,
    const float* __restrict__ nw2, const float* __restrict__ nb2,
    const float* __restrict__ nw3, const float* __restrict__ nb3,
    float* __restrict__ out)
{
    extern __shared__ float sm[];
    const int b   = blockIdx.x;
    const int tid = threadIdx.x;

    // ---- stage inputs / weights into shared memory ----
    const float* xsb = xs + b * 32 * 256;
    for (int m = tid; m < 32 * 256; m += NTHREADS) {
        int e = m >> 8, d = m & 255;
        sm[OFF_XT + d * 33 + e] = xsb[m];      // transposed + padded
    }
    scopy(sm + OFF_W1,  ew1, 256 * 40, tid);
    scopy(sm + OFF_EB1, eb1, 40, tid);
    scopy(sm + OFF_W2,  ew2, 40 * 6, tid);
    scopy(sm + OFF_EB2, eb2, 6, tid);
    scopy(sm + OFF_W3,  ew3, 6, tid);
    scopy(sm + OFF_EB3, eb3, 1, tid);
    scopy(sm + OFF_NW1, nw1, 256 * 81, tid);
    scopy(sm + OFF_NB1, nb1, 81, tid);
    scopy(sm + OFF_NW2, nw2, 81 * 25, tid);
    scopy(sm + OFF_NB2, nb2, 25, tid);
    scopy(sm + OFF_NW3, nw3, 25 * 8, tid);
    scopy(sm + OFF_NB3, nb3, 8, tid);
    scopy(sm + OFF_RS,  rs + b * 96, 96, tid);
    scopy(sm + OFF_CRD, coords, 24, tid);
    __syncthreads();

    // ---- nucleus MLP: 256 -> 81 -> 25 -> 8 ----
    for (int idx = tid; idx < 32 * 81; idx += NTHREADS) {
        int i = idx / 81, f = idx % 81;
        float s = sm[OFF_NB1 + f];
        #pragma unroll 4
        for (int d = 0; d < 256; ++d)
            s += sm[OFF_XT + d * 33 + i] * sm[OFF_NW1 + d * 81 + f];
        sm[OFF_H1N + idx] = ssp(s);
    }
    __syncthreads();
    for (int idx = tid; idx < 32 * 25; idx += NTHREADS) {
        int i = idx / 25, c = idx % 25;
        float s = sm[OFF_NB2 + c];
        #pragma unroll
        for (int f = 0; f < 81; ++f)
            s += sm[OFF_H1N + i * 81 + f] * sm[OFF_NW2 + f * 25 + c];
        sm[OFF_H2N + idx] = ssp(s);
    }
    __syncthreads();
    for (int idx = tid; idx < 32 * 8; idx += NTHREADS) {
        int i = idx / 8, k = idx % 8;
        float s = sm[OFF_NB3 + k];
        #pragma unroll
        for (int c = 0; c < 25; ++c)
            s += sm[OFF_H2N + i * 25 + c] * sm[OFF_NW3 + c * 8 + k];
        sm[OFF_WN + idx] = s;
    }
    __syncthreads();

    // ---- bf_nuc + cutoff (one thread per electron) ----
    if (tid < 32) {
        const int i = tid;
        float rx = sm[OFF_RS + i * 3 + 0];
        float ry = sm[OFF_RS + i * 3 + 1];
        float rz = sm[OFF_RS + i * 3 + 2];
        float bx = 0.f, by = 0.f, bz = 0.f, cut = 1.f;
        #pragma unroll
        for (int k = 0; k < 8; ++k) {
            float dx = rx - sm[OFF_CRD + k * 3 + 0];
            float dy = ry - sm[OFF_CRD + k * 3 + 1];
            float dz = rz - sm[OFF_CRD + k * 3 + 2];
            float dist = sqrtf(dx * dx + dy * dy + dz * dz);
            // reference: r = dist/0.5; where(r < 0.5, r^2(6-8r+3r^2), 1)
            float rr = dist * 2.0f;
            float cv = (rr < 0.5f) ? rr * rr * (6.0f - 8.0f * rr + 3.0f * rr * rr) : 1.0f;
            cut *= cv;
            float wk = sm[OFF_WN + i * 8 + k];
            bx += wk * dx; by += wk * dy; bz += wk * dz;
        }
        sm[OFF_BFN + i * 3 + 0] = bx;
        sm[OFF_BFN + i * 3 + 1] = by;
        sm[OFF_BFN + i * 3 + 2] = bz;
        sm[OFF_CUT + i] = cut;
    }
    __syncthreads();

    // ---- electron-electron pair MLP, fused ----
    // Warp handles electrons i0=warp, i1=warp+16; lane = j. W1 LDS shared across both i.
    const int warp = tid >> 5, lane = tid & 31;
    const int i0 = warp, i1 = warp + 16;

    float acc0[40], acc1[40];
    #pragma unroll
    for (int f = 0; f < 40; ++f) { acc0[f] = 0.f; acc1[f] = 0.f; }

    const float* XT = sm + OFF_XT;
    const float* W1 = sm + OFF_W1;

    #pragma unroll 2
    for (int d = 0; d < 256; ++d) {
        float xj = XT[d * 33 + lane];
        float p0 = XT[d * 33 + i0] * xj;
        float p1 = XT[d * 33 + i1] * xj;
        const float4* wr = reinterpret_cast<const float4*>(W1 + d * 40);
        #pragma unroll
        for (int q = 0; q < 10; ++q) {
            float4 w = wr[q];
            acc0[4 * q + 0] += p0 * w.x;  acc1[4 * q + 0] += p1 * w.x;
            acc0[4 * q + 1] += p0 * w.y;  acc1[4 * q + 1] += p1 * w.y;
            acc0[4 * q + 2] += p0 * w.z;  acc1[4 * q + 2] += p1 * w.z;
            acc0[4 * q + 3] += p0 * w.w;  acc1[4 * q + 3] += p1 * w.w;
        }
    }

    pair_epilogue(acc0, i0, lane, sm, out, b);
    pair_epilogue(acc1, i1, lane, sm, out, b);
}

extern "C" void kernel_launch(void* const* d_in, const int* in_sizes, int n_in,
                              void* d_out, int out_size)
{
    const float* rs     = (const float*)d_in[0];
    const float* xs     = (const float*)d_in[1];
    const float* coords = (const float*)d_in[2];
    const float* ew1    = (const float*)d_in[3];
    const float* eb1    = (const float*)d_in[4];
    const float* ew2    = (const float*)d_in[5];
    const float* eb2    = (const float*)d_in[6];
    const float* ew3    = (const float*)d_in[7];
    const float* eb3    = (const float*)d_in[8];
    const float* nw1    = (const float*)d_in[9];
    const float* nb1    = (const float*)d_in[10];
    const float* nw2    = (const float*)d_in[11];
    const float* nb2    = (const float*)d_in[12];
    const float* nw3    = (const float*)d_in[13];
    const float* nb3    = (const float*)d_in[14];
    float* out = (float*)d_out;

    int B = in_sizes[0] / 96;   // rs is [B,32,3]

    cudaFuncSetAttribute(backflow_kernel,
                         cudaFuncAttributeMaxDynamicSharedMemorySize, SMEM_BYTES);
    backflow_kernel<<<B, NTHREADS, SMEM_BYTES>>>(
        rs, xs, coords, ew1, eb1, ew2, eb2, ew3, eb3,
        nw1, nb1, nw2, nb2, nw3, nb3, out);
}

// round 6
// speedup vs baseline: 1.2385x; 1.2385x over previous
#include <cuda_runtime.h>
#include <cstdint>

// Backflow fused kernel, round 2: f32x2 packed FFMA main loop + restructured
// nucleus MLP + fast ssp. One CTA per batch element.
// B=512, N=32 electrons, D=256 features, K=8 nuclei.

#define NTHREADS 512

// ---- shared memory layout (float offsets) ----
constexpr int OFF_XT   = 0;            // X transposed, padded: [256][33]
constexpr int OFF_W1   = 8448;         // ew1 [256][40]  (16B-aligned rows of 160B)
constexpr int OFF_EB1  = 18688;        // 40
constexpr int OFF_W2   = 18728;        // ew2 [40][6]
constexpr int OFF_EB2  = 18968;        // 6
constexpr int OFF_W3   = 18974;        // ew3 [6]
constexpr int OFF_EB3  = 18980;        // 1 (pad to 18984)
constexpr int OFF_NW1  = 18984;        // nw1 [256][81]
constexpr int OFF_NB1  = 39720;        // 81 (pad to 39804)
constexpr int OFF_NW2  = 39804;        // nw2 [81][25]
constexpr int OFF_NB2  = 41829;        // 25 (pad to 41856)
constexpr int OFF_NW3  = 41856;        // nw3 [25][8]
constexpr int OFF_NB3  = 42056;        // 8
constexpr int OFF_H1T  = 42064;        // nuc hidden1 transposed [81][33]
constexpr int OFF_H2T  = 44740;        // nuc hidden2 transposed [25][33]
constexpr int OFF_WN   = 45568;        // w_nuc [32][8]
constexpr int OFF_RS   = 45824;        // rs[b] [32][3]
constexpr int OFF_CRD  = 45920;        // coords [8][3]
constexpr int OFF_BFN  = 45944;        // bf_nuc [32][3]
constexpr int OFF_CUT  = 46040;        // cutoff [32]
constexpr int SMEM_FLOATS = 46072;
constexpr int SMEM_BYTES  = SMEM_FLOATS * 4;   // 184288 B

// shifted softplus: log(0.5*exp(x)+0.5). Fast MUFU path + large-x guard.
__device__ __forceinline__ float ssp(float x) {
    float r = __logf(fmaf(0.5f, __expf(x), 0.5f));
    return (x > 60.0f) ? (x - 0.69314718056f) : r;
}

__device__ __forceinline__ uint64_t pk2(float a, float b) {
    uint64_t r;
    asm("mov.b64 %0, {%1, %2};" : "=l"(r) : "f"(a), "f"(b));
    return r;
}
__device__ __forceinline__ void upk2(uint64_t v, float& lo, float& hi) {
    asm("mov.b64 {%0, %1}, %2;" : "=f"(lo), "=f"(hi) : "l"(v));
}
__device__ __forceinline__ void fma2(uint64_t& d, uint64_t a, uint64_t b) {
    asm("fma.rn.f32x2 %0, %1, %2, %0;" : "+l"(d) : "l"(a), "l"(b));
}

__device__ __forceinline__ void scopy(float* dst, const float* src, int n, int tid) {
    for (int t = tid; t < n; t += NTHREADS) dst[t] = src[t];
}

// Pair-MLP layers 2/3 + reduction + output write for one electron i.
__device__ __forceinline__ void pair_epilogue(
    const uint64_t* __restrict__ acc, int i, int lane, const float* __restrict__ sm,
    float* __restrict__ out, int b)
{
    float h2[6];
    #pragma unroll
    for (int c = 0; c < 6; ++c) h2[c] = sm[OFF_EB2 + c];
    #pragma unroll
    for (int p = 0; p < 20; ++p) {
        float lo, hi;
        upk2(acc[p], lo, hi);
        float h0 = ssp(lo + sm[OFF_EB1 + 2 * p + 0]);
        float h1 = ssp(hi + sm[OFF_EB1 + 2 * p + 1]);
        #pragma unroll
        for (int c = 0; c < 6; ++c) {
            h2[c] = fmaf(h0, sm[OFF_W2 + (2 * p + 0) * 6 + c], h2[c]);
            h2[c] = fmaf(h1, sm[OFF_W2 + (2 * p + 1) * 6 + c], h2[c]);
        }
    }
    float w = sm[OFF_EB3];
    #pragma unroll
    for (int c = 0; c < 6; ++c) w = fmaf(ssp(h2[c]), sm[OFF_W3 + c], w);

    float rix = sm[OFF_RS + i * 3 + 0];
    float riy = sm[OFF_RS + i * 3 + 1];
    float riz = sm[OFF_RS + i * 3 + 2];
    float dx = rix - sm[OFF_RS + lane * 3 + 0];
    float dy = riy - sm[OFF_RS + lane * 3 + 1];
    float dz = riz - sm[OFF_RS + lane * 3 + 2];
    if (lane == i) w = 0.0f;

    float cx = w * dx, cy = w * dy, cz = w * dz;
    #pragma unroll
    for (int off = 16; off; off >>= 1) {
        cx += __shfl_down_sync(0xffffffffu, cx, off);
        cy += __shfl_down_sync(0xffffffffu, cy, off);
        cz += __shfl_down_sync(0xffffffffu, cz, off);
    }
    if (lane == 0) {
        float s  = 1e-4f * sm[OFF_CUT + i];
        out[b * 96 + i * 3 + 0] = fmaf(s, cx + sm[OFF_BFN + i * 3 + 0], rix);
        out[b * 96 + i * 3 + 1] = fmaf(s, cy + sm[OFF_BFN + i * 3 + 1], riy);
        out[b * 96 + i * 3 + 2] = fmaf(s, cz + sm[OFF_BFN + i * 3 + 2], riz);
    }
}

__global__ __launch_bounds__(NTHREADS, 1)
void backflow_kernel(
    const float* __restrict__ rs, const float* __restrict__ xs, const float* __restrict__ coords,
    const float* __restrict__ ew1, const float* __restrict__ eb1,
    const float* __restrict__ ew2, const float* __restrict__ eb2,
    const float* __restrict__ ew3, const float* __restrict__ eb3,
    const float* __restrict__ nw1, const float* __restrict__ nb1,
    const float* __restrict__ nw2, const float* __restrict__ nb2,
    const float* __restrict__ nw3, const float* __restrict__ nb3,
    float* __restrict__ out)
{
    extern __shared__ float sm[];
    const int b    = blockIdx.x;
    const int tid  = threadIdx.x;
    const int warp = tid >> 5, lane = tid & 31;

    // ---- stage ----
    const float* xsb = xs + b * 32 * 256;
    for (int m = tid; m < 32 * 256; m += NTHREADS) {
        int e = m >> 8, d = m & 255;
        sm[OFF_XT + d * 33 + e] = xsb[m];
    }
    scopy(sm + OFF_W1,  ew1, 256 * 40, tid);
    scopy(sm + OFF_EB1, eb1, 40, tid);
    scopy(sm + OFF_W2,  ew2, 40 * 6, tid);
    scopy(sm + OFF_EB2, eb2, 6, tid);
    scopy(sm + OFF_W3,  ew3, 6, tid);
    scopy(sm + OFF_EB3, eb3, 1, tid);
    scopy(sm + OFF_NW1, nw1, 256 * 81, tid);
    scopy(sm + OFF_NB1, nb1, 81, tid);
    scopy(sm + OFF_NW2, nw2, 81 * 25, tid);
    scopy(sm + OFF_NB2, nb2, 25, tid);
    scopy(sm + OFF_NW3, nw3, 25 * 8, tid);
    scopy(sm + OFF_NB3, nb3, 8, tid);
    scopy(sm + OFF_RS,  rs + b * 96, 96, tid);
    scopy(sm + OFF_CRD, coords, 24, tid);
    __syncthreads();

    // ---- nucleus MLP layer 1: 256 -> 81.  lane = electron, warp owns f stripe. ----
    {
        float ac[6];
        int   fi[6];
        #pragma unroll
        for (int c = 0; c < 6; ++c) {
            int f = warp + 16 * c;
            fi[c] = f;
            int fs = (f < 81) ? f : 0;
            ac[c] = sm[OFF_NB1 + fs];
        }
        #pragma unroll 4
        for (int d = 0; d < 256; ++d) {
            float xi = sm[OFF_XT + d * 33 + lane];
            #pragma unroll
            for (int c = 0; c < 6; ++c) {
                int fs = (fi[c] < 81) ? fi[c] : 0;
                ac[c] = fmaf(xi, sm[OFF_NW1 + d * 81 + fs], ac[c]);
            }
        }
        #pragma unroll
        for (int c = 0; c < 6; ++c)
            if (fi[c] < 81) sm[OFF_H1T + fi[c] * 33 + lane] = ssp(ac[c]);
    }
    __syncthreads();

    // ---- nucleus layer 2: 81 -> 25 ----
    {
        int c0 = warp, c1 = warp + 16;
        float a0 = sm[OFF_NB2 + c0];
        float a1 = (c1 < 25) ? sm[OFF_NB2 + c1] : 0.0f;
        int c1s = (c1 < 25) ? c1 : 0;
        #pragma unroll 3
        for (int f = 0; f < 81; ++f) {
            float h = sm[OFF_H1T + f * 33 + lane];
            a0 = fmaf(h, sm[OFF_NW2 + f * 25 + c0], a0);
            a1 = fmaf(h, sm[OFF_NW2 + f * 25 + c1s], a1);
        }
        sm[OFF_H2T + c0 * 33 + lane] = ssp(a0);
        if (c1 < 25) sm[OFF_H2T + c1 * 33 + lane] = ssp(a1);
    }
    __syncthreads();

    // ---- nucleus layer 3: 25 -> 8 ----
    if (warp < 8) {
        int k = warp;
        float a = sm[OFF_NB3 + k];
        #pragma unroll
        for (int c = 0; c < 25; ++c)
            a = fmaf(sm[OFF_H2T + c * 33 + lane], sm[OFF_NW3 + c * 8 + k], a);
        sm[OFF_WN + lane * 8 + k] = a;
    }
    __syncthreads();

    // ---- bf_nuc + cutoff ----
    if (tid < 32) {
        const int i = tid;
        float rx = sm[OFF_RS + i * 3 + 0];
        float ry = sm[OFF_RS + i * 3 + 1];
        float rz = sm[OFF_RS + i * 3 + 2];
        float bx = 0.f, by = 0.f, bz = 0.f, cut = 1.f;
        #pragma unroll
        for (int k = 0; k < 8; ++k) {
            float dx = rx - sm[OFF_CRD + k * 3 + 0];
            float dy = ry - sm[OFF_CRD + k * 3 + 1];
            float dz = rz - sm[OFF_CRD + k * 3 + 2];
            float dist = sqrtf(dx * dx + dy * dy + dz * dz);
            float rr = dist * 2.0f;
            float cv = (rr < 0.5f) ? rr * rr * (6.0f - 8.0f * rr + 3.0f * rr * rr) : 1.0f;
            cut *= cv;
            float wk = sm[OFF_WN + i * 8 + k];
            bx = fmaf(wk, dx, bx); by = fmaf(wk, dy, by); bz = fmaf(wk, dz, bz);
        }
        sm[OFF_BFN + i * 3 + 0] = bx;
        sm[OFF_BFN + i * 3 + 1] = by;
        sm[OFF_BFN + i * 3 + 2] = bz;
        sm[OFF_CUT + i] = cut;
    }
    __syncthreads();

    // ---- pair MLP layer 1, f32x2 packed. warp owns i0=warp, i1=warp+16; lane = j. ----
    const int i0 = warp, i1 = warp + 16;

    uint64_t acc0[20], acc1[20];
    #pragma unroll
    for (int q = 0; q < 20; ++q) { acc0[q] = 0ull; acc1[q] = 0ull; }

    const float* XT = sm + OFF_XT;

    #pragma unroll 2
    for (int d = 0; d < 256; ++d) {
        float xj = XT[d * 33 + lane];
        float p0 = XT[d * 33 + i0] * xj;
        float p1 = XT[d * 33 + i1] * xj;
        uint64_t pp0 = pk2(p0, p0);
        uint64_t pp1 = pk2(p1, p1);
        const ulonglong2* wr = reinterpret_cast<const ulonglong2*>(sm + OFF_W1 + d * 40);
        #pragma unroll
        for (int q = 0; q < 10; ++q) {
            ulonglong2 w = wr[q];
            fma2(acc0[2 * q + 0], pp0, w.x);
            fma2(acc0[2 * q + 1], pp0, w.y);
            fma2(acc1[2 * q + 0], pp1, w.x);
            fma2(acc1[2 * q + 1], pp1, w.y);
        }
    }

    pair_epilogue(acc0, i0, lane, sm, out, b);
    pair_epilogue(acc1, i1, lane, sm, out, b);
}

extern "C" void kernel_launch(void* const* d_in, const int* in_sizes, int n_in,
                              void* d_out, int out_size)
{
    const float* rs     = (const float*)d_in[0];
    const float* xs     = (const float*)d_in[1];
    const float* coords = (const float*)d_in[2];
    const float* ew1    = (const float*)d_in[3];
    const float* eb1    = (const float*)d_in[4];
    const float* ew2    = (const float*)d_in[5];
    const float* eb2    = (const float*)d_in[6];
    const float* ew3    = (const float*)d_in[7];
    const float* eb3    = (const float*)d_in[8];
    const float* nw1    = (const float*)d_in[9];
    const float* nb1    = (const float*)d_in[10];
    const float* nw2    = (const float*)d_in[11];
    const float* nb2    = (const float*)d_in[12];
    const float* nw3    = (const float*)d_in[13];
    const float* nb3    = (const float*)d_in[14];
    float* out = (float*)d_out;

    int B = in_sizes[0] / 96;

    cudaFuncSetAttribute(backflow_kernel,
                         cudaFuncAttributeMaxDynamicSharedMemorySize, SMEM_BYTES);
    backflow_kernel<<<B, NTHREADS, SMEM_BYTES>>>(
        rs, xs, coords, ew1, eb1, ew2, eb2, ew3, eb3,
        nw1, nb1, nw2, nb2, nw3, nb3, out);
}

// round 7
// speedup vs baseline: 1.6878x; 1.3629x over previous
#include <cuda_runtime.h>
#include <cstdint>

// Backflow fused kernel, round 3: exploit w_pair symmetry (w(i,j)=w(j,i)) —
// one thread per UNORDERED pair via round-robin tournament mapping.
// Halves the dominant pair-MLP work. f32x2 packed FFMA layer 1.
// One CTA per batch element. B=512, N=32, D=256, K=8.

#define NTHREADS 512

// ---- shared memory layout (float offsets) ----
constexpr int OFF_XT   = 0;            // X transposed, padded: [256][33]
constexpr int OFF_W1   = 8448;         // ew1 [256][40]
constexpr int OFF_EB1  = 18688;        // 40
constexpr int OFF_W2   = 18728;        // ew2 [40][6]
constexpr int OFF_EB2  = 18968;        // 6
constexpr int OFF_W3   = 18974;        // ew3 [6]
constexpr int OFF_EB3  = 18980;        // 1 (pad to 18984)
constexpr int OFF_NW1  = 18984;        // nw1 [256][81]
constexpr int OFF_NB1  = 39720;        // 81 (pad to 39804)
constexpr int OFF_NW2  = 39804;        // nw2 [81][25]
constexpr int OFF_NB2  = 41829;        // 25 (pad to 41856)
constexpr int OFF_NW3  = 41856;        // nw3 [25][8]
constexpr int OFF_NB3  = 42056;        // 8
constexpr int OFF_H1T  = 42064;        // nuc hidden1 transposed [81][33]
constexpr int OFF_H2T  = 44740;        // nuc hidden2 transposed [25][33]
constexpr int OFF_WN   = 45568;        // w_nuc [32][8]
constexpr int OFF_RS   = 45824;        // rs[b] [32][3]
constexpr int OFF_CRD  = 45920;        // coords [8][3]
constexpr int OFF_BFN  = 45944;        // bf accumulators [32][3]
constexpr int OFF_CUT  = 46040;        // cutoff [32]
constexpr int SMEM_FLOATS = 46072;
constexpr int SMEM_BYTES  = SMEM_FLOATS * 4;   // 184288 B

// shifted softplus: log(0.5*exp(x)+0.5). Fast MUFU path + large-x guard.
__device__ __forceinline__ float ssp(float x) {
    float r = __logf(fmaf(0.5f, __expf(x), 0.5f));
    return (x > 60.0f) ? (x - 0.69314718056f) : r;
}

__device__ __forceinline__ uint64_t pk2(float a, float b) {
    uint64_t r;
    asm("mov.b64 %0, {%1, %2};" : "=l"(r) : "f"(a), "f"(b));
    return r;
}
__device__ __forceinline__ void upk2(uint64_t v, float& lo, float& hi) {
    asm("mov.b64 {%0, %1}, %2;" : "=f"(lo), "=f"(hi) : "l"(v));
}
__device__ __forceinline__ void fma2(uint64_t& d, uint64_t a, uint64_t b) {
    asm("fma.rn.f32x2 %0, %1, %2, %0;" : "+l"(d) : "l"(a), "l"(b));
}

__device__ __forceinline__ void scopy(float* dst, const float* src, int n, int tid) {
    for (int t = tid; t < n; t += NTHREADS) dst[t] = src[t];
}

__global__ __launch_bounds__(NTHREADS, 1)
void backflow_kernel(
    const float* __restrict__ rs, const float* __restrict__ xs, const float* __restrict__ coords,
    const float* __restrict__ ew1, const float* __restrict__ eb1,
    const float* __restrict__ ew2, const float* __restrict__ eb2,
    const float* __restrict__ ew3, const float* __restrict__ eb3,
    const float* __restrict__ nw1, const float* __restrict__ nb1,
    const float* __restrict__ nw2, const float* __restrict__ nb2,
    const float* __restrict__ nw3, const float* __restrict__ nb3,
    float* __restrict__ out)
{
    extern __shared__ float sm[];
    const int b    = blockIdx.x;
    const int tid  = threadIdx.x;
    const int warp = tid >> 5, lane = tid & 31;

    // ---- stage ----
    const float* xsb = xs + b * 32 * 256;
    for (int m = tid; m < 32 * 256; m += NTHREADS) {
        int e = m >> 8, d = m & 255;
        sm[OFF_XT + d * 33 + e] = xsb[m];
    }
    scopy(sm + OFF_W1,  ew1, 256 * 40, tid);
    scopy(sm + OFF_EB1, eb1, 40, tid);
    scopy(sm + OFF_W2,  ew2, 40 * 6, tid);
    scopy(sm + OFF_EB2, eb2, 6, tid);
    scopy(sm + OFF_W3,  ew3, 6, tid);
    scopy(sm + OFF_EB3, eb3, 1, tid);
    scopy(sm + OFF_NW1, nw1, 256 * 81, tid);
    scopy(sm + OFF_NB1, nb1, 81, tid);
    scopy(sm + OFF_NW2, nw2, 81 * 25, tid);
    scopy(sm + OFF_NB2, nb2, 25, tid);
    scopy(sm + OFF_NW3, nw3, 25 * 8, tid);
    scopy(sm + OFF_NB3, nb3, 8, tid);
    scopy(sm + OFF_RS,  rs + b * 96, 96, tid);
    scopy(sm + OFF_CRD, coords, 24, tid);
    __syncthreads();

    // ---- nucleus MLP layer 1: 256 -> 81.  lane = electron, warp owns f stripe. ----
    {
        float ac[6];
        int   fi[6];
        #pragma unroll
        for (int c = 0; c < 6; ++c) {
            int f = warp + 16 * c;
            fi[c] = f;
            int fs = (f < 81) ? f : 0;
            ac[c] = sm[OFF_NB1 + fs];
        }
        #pragma unroll 4
        for (int d = 0; d < 256; ++d) {
            float xi = sm[OFF_XT + d * 33 + lane];
            #pragma unroll
            for (int c = 0; c < 6; ++c) {
                int fs = (fi[c] < 81) ? fi[c] : 0;
                ac[c] = fmaf(xi, sm[OFF_NW1 + d * 81 + fs], ac[c]);
            }
        }
        #pragma unroll
        for (int c = 0; c < 6; ++c)
            if (fi[c] < 81) sm[OFF_H1T + fi[c] * 33 + lane] = ssp(ac[c]);
    }
    __syncthreads();

    // ---- nucleus layer 2: 81 -> 25 ----
    {
        int c0 = warp, c1 = warp + 16;
        float a0 = sm[OFF_NB2 + c0];
        float a1 = (c1 < 25) ? sm[OFF_NB2 + c1] : 0.0f;
        int c1s = (c1 < 25) ? c1 : 0;
        #pragma unroll 3
        for (int f = 0; f < 81; ++f) {
            float h = sm[OFF_H1T + f * 33 + lane];
            a0 = fmaf(h, sm[OFF_NW2 + f * 25 + c0], a0);
            a1 = fmaf(h, sm[OFF_NW2 + f * 25 + c1s], a1);
        }
        sm[OFF_H2T + c0 * 33 + lane] = ssp(a0);
        if (c1 < 25) sm[OFF_H2T + c1 * 33 + lane] = ssp(a1);
    }
    __syncthreads();

    // ---- nucleus layer 3: 25 -> 8 ----
    if (warp < 8) {
        int k = warp;
        float a = sm[OFF_NB3 + k];
        #pragma unroll
        for (int c = 0; c < 25; ++c)
            a = fmaf(sm[OFF_H2T + c * 33 + lane], sm[OFF_NW3 + c * 8 + k], a);
        sm[OFF_WN + lane * 8 + k] = a;
    }
    __syncthreads();

    // ---- bf_nuc + cutoff ----
    if (tid < 32) {
        const int i = tid;
        float rx = sm[OFF_RS + i * 3 + 0];
        float ry = sm[OFF_RS + i * 3 + 1];
        float rz = sm[OFF_RS + i * 3 + 2];
        float bx = 0.f, by = 0.f, bz = 0.f, cut = 1.f;
        #pragma unroll
        for (int k = 0; k < 8; ++k) {
            float dx = rx - sm[OFF_CRD + k * 3 + 0];
            float dy = ry - sm[OFF_CRD + k * 3 + 1];
            float dz = rz - sm[OFF_CRD + k * 3 + 2];
            float dist = sqrtf(dx * dx + dy * dy + dz * dz);
            float rr = dist * 2.0f;
            float cv = (rr < 0.5f) ? rr * rr * (6.0f - 8.0f * rr + 3.0f * rr * rr) : 1.0f;
            cut *= cv;
            float wk = sm[OFF_WN + i * 8 + k];
            bx = fmaf(wk, dx, bx); by = fmaf(wk, dy, by); bz = fmaf(wk, dz, bz);
        }
        sm[OFF_BFN + i * 3 + 0] = bx;   // seeds the pair scatter-add below
        sm[OFF_BFN + i * 3 + 1] = by;
        sm[OFF_BFN + i * 3 + 2] = bz;
        sm[OFF_CUT + i] = cut;
    }
    __syncthreads();

    // ---- pair MLP: one thread per UNORDERED pair (round-robin tournament) ----
    // Round r in [0,31): pair (31, r) for m=0, and ((r+m)%31, (r+31-m)%31) for m=1..15.
    // Covers each unordered pair of {0..31} exactly once: 31*16 = 496 pairs.
    const int r = tid >> 4;
    const int m = tid & 15;
    const bool valid = (r < 31);
    int pi, pj;
    if (m == 0) { pi = 31; pj = valid ? r : 0; }
    else {
        int rr = valid ? r : 0;
        pi = (rr + m) % 31;
        pj = (rr + 31 - m) % 31;
    }

    uint64_t acc[20];
    #pragma unroll
    for (int q = 0; q < 20; ++q) acc[q] = 0ull;

    const float* XT = sm + OFF_XT;

    #pragma unroll 2
    for (int d = 0; d < 256; ++d) {
        float xi = XT[d * 33 + pi];
        float xj = XT[d * 33 + pj];
        float p  = xi * xj;
        uint64_t pp = pk2(p, p);
        const ulonglong2* wr = reinterpret_cast<const ulonglong2*>(sm + OFF_W1 + d * 40);
        #pragma unroll
        for (int q = 0; q < 10; ++q) {
            ulonglong2 w = wr[q];
            fma2(acc[2 * q + 0], pp, w.x);
            fma2(acc[2 * q + 1], pp, w.y);
        }
    }

    // ---- layers 2/3 per pair ----
    float h2[6];
    #pragma unroll
    for (int c = 0; c < 6; ++c) h2[c] = sm[OFF_EB2 + c];
    #pragma unroll
    for (int p = 0; p < 20; ++p) {
        float lo, hi;
        upk2(acc[p], lo, hi);
        float h0 = ssp(lo + sm[OFF_EB1 + 2 * p + 0]);
        float h1 = ssp(hi + sm[OFF_EB1 + 2 * p + 1]);
        #pragma unroll
        for (int c = 0; c < 6; ++c) {
            h2[c] = fmaf(h0, sm[OFF_W2 + (2 * p + 0) * 6 + c], h2[c]);
            h2[c] = fmaf(h1, sm[OFF_W2 + (2 * p + 1) * 6 + c], h2[c]);
        }
    }
    float w = sm[OFF_EB3];
    #pragma unroll
    for (int c = 0; c < 6; ++c) w = fmaf(ssp(h2[c]), sm[OFF_W3 + c], w);
    if (!valid) w = 0.0f;

    // ---- scatter-add +- w * (r_i - r_j) ----
    float dx = sm[OFF_RS + pi * 3 + 0] - sm[OFF_RS + pj * 3 + 0];
    float dy = sm[OFF_RS + pi * 3 + 1] - sm[OFF_RS + pj * 3 + 1];
    float dz = sm[OFF_RS + pi * 3 + 2] - sm[OFF_RS + pj * 3 + 2];
    float cx = w * dx, cy = w * dy, cz = w * dz;
    atomicAdd(&sm[OFF_BFN + pi * 3 + 0],  cx);
    atomicAdd(&sm[OFF_BFN + pi * 3 + 1],  cy);
    atomicAdd(&sm[OFF_BFN + pi * 3 + 2],  cz);
    atomicAdd(&sm[OFF_BFN + pj * 3 + 0], -cx);
    atomicAdd(&sm[OFF_BFN + pj * 3 + 1], -cy);
    atomicAdd(&sm[OFF_BFN + pj * 3 + 2], -cz);
    __syncthreads();

    // ---- final output ----
    if (tid < 96) {
        int i = tid / 3, c = tid % 3;
        float s = 1e-4f * sm[OFF_CUT + i];
        out[b * 96 + tid] = fmaf(s, sm[OFF_BFN + tid], sm[OFF_RS + tid]);
    }
}

extern "C" void kernel_launch(void* const* d_in, const int* in_sizes, int n_in,
                              void* d_out, int out_size)
{
    const float* rs     = (const float*)d_in[0];
    const float* xs     = (const float*)d_in[1];
    const float* coords = (const float*)d_in[2];
    const float* ew1    = (const float*)d_in[3];
    const float* eb1    = (const float*)d_in[4];
    const float* ew2    = (const float*)d_in[5];
    const float* eb2    = (const float*)d_in[6];
    const float* ew3    = (const float*)d_in[7];
    const float* eb3    = (const float*)d_in[8];
    const float* nw1    = (const float*)d_in[9];
    const float* nb1    = (const float*)d_in[10];
    const float* nw2    = (const float*)d_in[11];
    const float* nb2    = (const float*)d_in[12];
    const float* nw3    = (const float*)d_in[13];
    const float* nb3    = (const float*)d_in[14];
    float* out = (float*)d_out;

    int B = in_sizes[0] / 96;

    cudaFuncSetAttribute(backflow_kernel,
                         cudaFuncAttributeMaxDynamicSharedMemorySize, SMEM_BYTES);
    backflow_kernel<<<B, NTHREADS, SMEM_BYTES>>>(
        rs, xs, coords, ew1, eb1, ew2, eb2, ew3, eb3,
        nw1, nb1, nw2, nb2, nw3, nb3, out);
}

// round 9
// speedup vs baseline: 1.7316x; 1.0259x over previous
#include <cuda_runtime.h>
#include <cstdint>

// Backflow fused kernel, round 5: 2 CTAs/SM occupancy build.
// - NW1 (81KB) read from gmem via warp-uniform __ldg broadcast (smem 184->99KB)
// - pair layer-1 in two 20-feature passes (acc regs 40->20, fits 64-reg cap)
// - f32x2 packed FFMA, unordered-pair tournament mapping (496 pairs)
// One CTA per batch element. B=512, N=32, D=256, K=8.

#define NTHREADS 512

// ---- shared memory layout (float offsets) ----
constexpr int OFF_XT  = 0;       // X transposed, padded [256][33]
constexpr int OFF_W1  = 8448;    // ew1 [256][40] (rows 160B, 16B-aligned)
constexpr int OFF_EB1 = 18688;   // 40
constexpr int OFF_W2  = 18728;   // ew2 [40][6]
constexpr int OFF_EB2 = 18968;   // 6
constexpr int OFF_W3  = 18974;   // 6
constexpr int OFF_EB3 = 18980;   // 1 (pad to 18984)
constexpr int OFF_NW2 = 18984;   // nw2 [81][25] = 2025
constexpr int OFF_NB2 = 21009;   // 25 (pad to 21036)
constexpr int OFF_NW3 = 21036;   // nw3 [25][8] = 200
constexpr int OFF_NB3 = 21236;   // 8
constexpr int OFF_NB1 = 21244;   // 81 (pad to 21328)
constexpr int OFF_H1T = 21328;   // [81][33] = 2673 (pad to 24004)
constexpr int OFF_H2T = 24004;   // [25][33] = 825 (pad to 24832)
constexpr int OFF_WN  = 24832;   // [32][8]
constexpr int OFF_RS  = 25088;   // 96
constexpr int OFF_CRD = 25184;   // 24
constexpr int OFF_BFN = 25208;   // 96
constexpr int OFF_CUT = 25304;   // 32
constexpr int SMEM_FLOATS = 25336;
constexpr int SMEM_BYTES  = SMEM_FLOATS * 4;   // 101344 B -> 2 CTAs/SM

// shifted softplus: log(0.5*exp(x)+0.5). Fast MUFU path + large-x guard.
__device__ __forceinline__ float ssp(float x) {
    float r = __logf(fmaf(0.5f, __expf(x), 0.5f));
    return (x > 60.0f) ? (x - 0.69314718056f) : r;
}

__device__ __forceinline__ uint64_t pk2(float a, float b) {
    uint64_t r;
    asm("mov.b64 %0, {%1, %2};" : "=l"(r) : "f"(a), "f"(b));
    return r;
}
__device__ __forceinline__ void upk2(uint64_t v, float& lo, float& hi) {
    asm("mov.b64 {%0, %1}, %2;" : "=f"(lo), "=f"(hi) : "l"(v));
}
__device__ __forceinline__ void fma2(uint64_t& d, uint64_t a, uint64_t b) {
    asm("fma.rn.f32x2 %0, %1, %2, %0;" : "+l"(d) : "l"(a), "l"(b));
}

__device__ __forceinline__ void scopy(float* dst, const float* src, int n, int tid) {
    for (int t = tid; t < n; t += NTHREADS) dst[t] = src[t];
}

// tournament mapping: pair p -> (pi, pj); 31 rounds x 16 = all 496 unordered pairs
__device__ __forceinline__ void pair_of(int p, int& pi, int& pj) {
    int r = p >> 4, m = p & 15;
    int rr = (r < 31) ? r : 0;
    if (m == 0) { pi = 31; pj = rr; }
    else { pi = (rr + m) % 31; pj = (rr + 31 - m) % 31; }
}

__global__ __launch_bounds__(NTHREADS, 2)
void backflow_kernel(
    const float* __restrict__ rs, const float* __restrict__ xs, const float* __restrict__ coords,
    const float* __restrict__ ew1, const float* __restrict__ eb1,
    const float* __restrict__ ew2, const float* __restrict__ eb2,
    const float* __restrict__ ew3, const float* __restrict__ eb3,
    const float* __restrict__ nw1, const float* __restrict__ nb1,
    const float* __restrict__ nw2, const float* __restrict__ nb2,
    const float* __restrict__ nw3, const float* __restrict__ nb3,
    float* __restrict__ out)
{
    extern __shared__ float sm[];
    const int b    = blockIdx.x;
    const int tid  = threadIdx.x;
    const int warp = tid >> 5, lane = tid & 31;

    // ---- stage (NW1 stays in gmem/L2) ----
    const float* xsb = xs + b * 32 * 256;
    for (int m = tid; m < 32 * 256; m += NTHREADS) {
        int e = m >> 8, d = m & 255;
        sm[OFF_XT + d * 33 + e] = xsb[m];
    }
    scopy(sm + OFF_W1,  ew1, 256 * 40, tid);
    scopy(sm + OFF_EB1, eb1, 40, tid);
    scopy(sm + OFF_W2,  ew2, 240, tid);
    scopy(sm + OFF_EB2, eb2, 6, tid);
    scopy(sm + OFF_W3,  ew3, 6, tid);
    scopy(sm + OFF_EB3, eb3, 1, tid);
    scopy(sm + OFF_NW2, nw2, 81 * 25, tid);
    scopy(sm + OFF_NB2, nb2, 25, tid);
    scopy(sm + OFF_NW3, nw3, 25 * 8, tid);
    scopy(sm + OFF_NB3, nb3, 8, tid);
    scopy(sm + OFF_NB1, nb1, 81, tid);
    scopy(sm + OFF_RS,  rs + b * 96, 96, tid);
    scopy(sm + OFF_CRD, coords, 24, tid);
    __syncthreads();

    // ---- nucleus MLP layer 1: 256 -> 81. lane = electron; warp owns 6 features.
    // NW1 weight address is warp-uniform -> __ldg broadcast from L2. ----
    {
        float ac[6]; int fi[6];
        #pragma unroll
        for (int c = 0; c < 6; ++c) {
            int f = warp + 16 * c; fi[c] = f;
            ac[c] = sm[OFF_NB1 + ((f < 81) ? f : 0)];
        }
        #pragma unroll 4
        for (int d = 0; d < 256; ++d) {
            float xi = sm[OFF_XT + d * 33 + lane];
            #pragma unroll
            for (int c = 0; c < 6; ++c) {
                int fs = (fi[c] < 81) ? fi[c] : 0;
                ac[c] = fmaf(xi, __ldg(nw1 + d * 81 + fs), ac[c]);
            }
        }
        #pragma unroll
        for (int c = 0; c < 6; ++c)
            if (fi[c] < 81) sm[OFF_H1T + fi[c] * 33 + lane] = ssp(ac[c]);
    }
    __syncthreads();

    // ---- nucleus layer 2: 81 -> 25 ----
    {
        int c0 = warp, c1 = warp + 16;
        float a0 = sm[OFF_NB2 + c0];
        float a1 = (c1 < 25) ? sm[OFF_NB2 + c1] : 0.0f;
        int c1s = (c1 < 25) ? c1 : 0;
        #pragma unroll 3
        for (int f = 0; f < 81; ++f) {
            float h = sm[OFF_H1T + f * 33 + lane];
            a0 = fmaf(h, sm[OFF_NW2 + f * 25 + c0], a0);
            a1 = fmaf(h, sm[OFF_NW2 + f * 25 + c1s], a1);
        }
        sm[OFF_H2T + c0 * 33 + lane] = ssp(a0);
        if (c1 < 25) sm[OFF_H2T + c1 * 33 + lane] = ssp(a1);
    }
    __syncthreads();

    // ---- nucleus layer 3: 25 -> 8 ----
    if (warp < 8) {
        int k = warp;
        float a = sm[OFF_NB3 + k];
        #pragma unroll
        for (int c = 0; c < 25; ++c)
            a = fmaf(sm[OFF_H2T + c * 33 + lane], sm[OFF_NW3 + c * 8 + k], a);
        sm[OFF_WN + lane * 8 + k] = a;
    }
    __syncthreads();

    // ---- bf_nuc + cutoff (seeds the scatter-add accumulator) ----
    if (tid < 32) {
        const int i = tid;
        float rx = sm[OFF_RS + i * 3 + 0], ry = sm[OFF_RS + i * 3 + 1], rz = sm[OFF_RS + i * 3 + 2];
        float bx = 0.f, by = 0.f, bz = 0.f, cut = 1.f;
        #pragma unroll
        for (int k = 0; k < 8; ++k) {
            float dx = rx - sm[OFF_CRD + k * 3 + 0];
            float dy = ry - sm[OFF_CRD + k * 3 + 1];
            float dz = rz - sm[OFF_CRD + k * 3 + 2];
            float dist = sqrtf(dx * dx + dy * dy + dz * dz);
            float rr = dist * 2.0f;
            float cv = (rr < 0.5f) ? rr * rr * (6.0f - 8.0f * rr + 3.0f * rr * rr) : 1.0f;
            cut *= cv;
            float wk = sm[OFF_WN + i * 8 + k];
            bx = fmaf(wk, dx, bx); by = fmaf(wk, dy, by); bz = fmaf(wk, dz, bz);
        }
        sm[OFF_BFN + i * 3 + 0] = bx;
        sm[OFF_BFN + i * 3 + 1] = by;
        sm[OFF_BFN + i * 3 + 2] = bz;
        sm[OFF_CUT + i] = cut;
    }
    __syncthreads();

    // ---- pair MLP: one thread per unordered pair; layer 1 in two 20-feature passes ----
    const bool valid = (tid < 496);
    int pi, pj;
    pair_of(tid, pi, pj);

    const float* XT = sm + OFF_XT;

    float h2[6];
    #pragma unroll
    for (int c = 0; c < 6; ++c) h2[c] = sm[OFF_EB2 + c];

    #pragma unroll 1
    for (int pass = 0; pass < 2; ++pass) {
        uint64_t acc[10];
        #pragma unroll
        for (int q = 0; q < 10; ++q) acc[q] = 0ull;

        const float* Wp = sm + OFF_W1 + pass * 20;
        #pragma unroll 2
        for (int d = 0; d < 256; ++d) {
            float xi = XT[d * 33 + pi];
            float xj = XT[d * 33 + pj];
            float pr = xi * xj;
            uint64_t pp = pk2(pr, pr);
            const ulonglong2* wr = reinterpret_cast<const ulonglong2*>(Wp + d * 40);
            #pragma unroll
            for (int q = 0; q < 5; ++q) {
                ulonglong2 w = wr[q];
                fma2(acc[2 * q + 0], pp, w.x);
                fma2(acc[2 * q + 1], pp, w.y);
            }
        }
        // fold this pass's 20 features into h2
        const float* eb1p = sm + OFF_EB1 + pass * 20;
        const float* w2p  = sm + OFF_W2 + pass * 20 * 6;
        #pragma unroll
        for (int q = 0; q < 10; ++q) {
            float lo, hi;
            upk2(acc[q], lo, hi);
            float h0 = ssp(lo + eb1p[2 * q + 0]);
            float h1 = ssp(hi + eb1p[2 * q + 1]);
            #pragma unroll
            for (int c = 0; c < 6; ++c) {
                h2[c] = fmaf(h0, w2p[(2 * q + 0) * 6 + c], h2[c]);
                h2[c] = fmaf(h1, w2p[(2 * q + 1) * 6 + c], h2[c]);
            }
        }
    }

    float w = sm[OFF_EB3];
    #pragma unroll
    for (int c = 0; c < 6; ++c) w = fmaf(ssp(h2[c]), sm[OFF_W3 + c], w);
    if (!valid) w = 0.0f;

    // ---- scatter-add +- w * (r_i - r_j) ----
    {
        float dx = sm[OFF_RS + pi * 3 + 0] - sm[OFF_RS + pj * 3 + 0];
        float dy = sm[OFF_RS + pi * 3 + 1] - sm[OFF_RS + pj * 3 + 1];
        float dz = sm[OFF_RS + pi * 3 + 2] - sm[OFF_RS + pj * 3 + 2];
        float cx = w * dx, cy = w * dy, cz = w * dz;
        atomicAdd(&sm[OFF_BFN + pi * 3 + 0],  cx);
        atomicAdd(&sm[OFF_BFN + pi * 3 + 1],  cy);
        atomicAdd(&sm[OFF_BFN + pi * 3 + 2],  cz);
        atomicAdd(&sm[OFF_BFN + pj * 3 + 0], -cx);
        atomicAdd(&sm[OFF_BFN + pj * 3 + 1], -cy);
        atomicAdd(&sm[OFF_BFN + pj * 3 + 2], -cz);
    }
    __syncthreads();

    // ---- final output ----
    if (tid < 96) {
        int i = tid / 3;
        float s = 1e-4f * sm[OFF_CUT + i];
        out[b * 96 + tid] = fmaf(s, sm[OFF_BFN + tid], sm[OFF_RS + tid]);
    }
}

extern "C" void kernel_launch(void* const* d_in, const int* in_sizes, int n_in,
                              void* d_out, int out_size)
{
    const float* rs     = (const float*)d_in[0];
    const float* xs     = (const float*)d_in[1];
    const float* coords = (const float*)d_in[2];
    const float* ew1    = (const float*)d_in[3];
    const float* eb1    = (const float*)d_in[4];
    const float* ew2    = (const float*)d_in[5];
    const float* eb2    = (const float*)d_in[6];
    const float* ew3    = (const float*)d_in[7];
    const float* eb3    = (const float*)d_in[8];
    const float* nw1    = (const float*)d_in[9];
    const float* nb1    = (const float*)d_in[10];
    const float* nw2    = (const float*)d_in[11];
    const float* nb2    = (const float*)d_in[12];
    const float* nw3    = (const float*)d_in[13];
    const float* nb3    = (const float*)d_in[14];
    float* out = (float*)d_out;

    int B = in_sizes[0] / 96;

    cudaFuncSetAttribute(backflow_kernel,
                         cudaFuncAttributeMaxDynamicSharedMemorySize, SMEM_BYTES);
    backflow_kernel<<<B, NTHREADS, SMEM_BYTES>>>(
        rs, xs, coords, ew1, eb1, ew2, eb2, ew3, eb3,
        nw1, nb1, nw2, nb2, nw3, nb3, out);
}

// round 11
// speedup vs baseline: 2.6058x; 1.5048x over previous
#include <cuda_runtime.h>
#include <cuda_bf16.h>
#include <cstdint>

// Backflow fused kernel, round 6: bf16-packed single-pass pair MLP (HFMA2),
// bf16 X shared with nucleus MLP, smem 63KB. One CTA per batch element.
// B=512, N=32, D=256, K=8. 496 unordered pairs via tournament mapping.

#define NTHREADS 512

// ---- shared memory layout (float/uint32 slot offsets) ----
constexpr int OFF_X2  = 0;       // bf16x2 [128 dpairs][32 electrons]  (4096 slots)
constexpr int OFF_W1B = 4096;    // bf16x2 [256 d][20 fpairs]          (5120 slots, 16B-aligned rows of 80B)
constexpr int OFF_EB1 = 9216;    // 40
constexpr int OFF_W2  = 9256;    // 240
constexpr int OFF_EB2 = 9496;    // 6
constexpr int OFF_W3  = 9502;    // 6
constexpr int OFF_EB3 = 9508;    // 1 (pad to 9512)
constexpr int OFF_NW2 = 9512;    // 2025
constexpr int OFF_NB2 = 11537;   // 25 (pad to 11564)
constexpr int OFF_NW3 = 11564;   // 200
constexpr int OFF_NB3 = 11764;   // 8
constexpr int OFF_NB1 = 11772;   // 81 (pad to 11856)
constexpr int OFF_H1T = 11856;   // [81][33] = 2673 (pad to 14532)
constexpr int OFF_H2T = 14532;   // [25][33] = 825 (pad to 15360)
constexpr int OFF_WN  = 15360;   // [32][8]
constexpr int OFF_RS  = 15616;   // 96
constexpr int OFF_CRD = 15712;   // 24
constexpr int OFF_BFN = 15736;   // 96
constexpr int OFF_CUT = 15832;   // 32
constexpr int SMEM_FLOATS = 15864;
constexpr int SMEM_BYTES  = SMEM_FLOATS * 4;   // 63456 B -> 2 CTAs/SM (regs are the 3-CTA blocker)

// shifted softplus: log(0.5*exp(x)+0.5). Fast MUFU path + large-x guard.
__device__ __forceinline__ float ssp(float x) {
    float r = __logf(fmaf(0.5f, __expf(x), 0.5f));
    return (x > 60.0f) ? (x - 0.69314718056f) : r;
}

__device__ __forceinline__ void scopy(float* dst, const float* src, int n, int tid) {
    for (int t = tid; t < n; t += NTHREADS) dst[t] = src[t];
}

__device__ __forceinline__ __nv_bfloat162 asbf2(uint32_t u) {
    return *reinterpret_cast<__nv_bfloat162*>(&u);
}

// tournament mapping: pair p -> (pi, pj); 31 rounds x 16 = all 496 unordered pairs
__device__ __forceinline__ void pair_of(int p, int& pi, int& pj) {
    int r = p >> 4, m = p & 15;
    int rr = (r < 31) ? r : 0;
    if (m == 0) { pi = 31; pj = rr; }
    else { pi = (rr + m) % 31; pj = (rr + 31 - m) % 31; }
}

__global__ __launch_bounds__(NTHREADS, 2)
void backflow_kernel(
    const float* __restrict__ rs, const float* __restrict__ xs, const float* __restrict__ coords,
    const float* __restrict__ ew1, const float* __restrict__ eb1,
    const float* __restrict__ ew2, const float* __restrict__ eb2,
    const float* __restrict__ ew3, const float* __restrict__ eb3,
    const float* __restrict__ nw1, const float* __restrict__ nb1,
    const float* __restrict__ nw2, const float* __restrict__ nb2,
    const float* __restrict__ nw3, const float* __restrict__ nb3,
    float* __restrict__ out)
{
    extern __shared__ float sm[];
    uint32_t* smu = reinterpret_cast<uint32_t*>(sm);
    const int b    = blockIdx.x;
    const int tid  = threadIdx.x;
    const int warp = tid >> 5, lane = tid & 31;

    // ---- stage ----
    // X2[dp][e] = bf16x2( x[e][2dp], x[e][2dp+1] )
    const float* xsb = xs + b * 32 * 256;
    for (int m = tid; m < 32 * 128; m += NTHREADS) {
        int e = m >> 7, dp = m & 127;
        float2 v = *reinterpret_cast<const float2*>(xsb + e * 256 + 2 * dp);
        __nv_bfloat162 pv = __floats2bfloat162_rn(v.x, v.y);
        smu[OFF_X2 + dp * 32 + e] = *reinterpret_cast<uint32_t*>(&pv);
    }
    // W1B[d][q] = bf16x2( ew1[d][2q], ew1[d][2q+1] )
    for (int m = tid; m < 256 * 20; m += NTHREADS) {
        int d = m / 20, q = m % 20;
        float2 v = *reinterpret_cast<const float2*>(ew1 + d * 40 + 2 * q);
        __nv_bfloat162 pv = __floats2bfloat162_rn(v.x, v.y);
        smu[OFF_W1B + d * 20 + q] = *reinterpret_cast<uint32_t*>(&pv);
    }
    scopy(sm + OFF_EB1, eb1, 40, tid);
    scopy(sm + OFF_W2,  ew2, 240, tid);
    scopy(sm + OFF_EB2, eb2, 6, tid);
    scopy(sm + OFF_W3,  ew3, 6, tid);
    scopy(sm + OFF_EB3, eb3, 1, tid);
    scopy(sm + OFF_NW2, nw2, 81 * 25, tid);
    scopy(sm + OFF_NB2, nb2, 25, tid);
    scopy(sm + OFF_NW3, nw3, 25 * 8, tid);
    scopy(sm + OFF_NB3, nb3, 8, tid);
    scopy(sm + OFF_NB1, nb1, 81, tid);
    scopy(sm + OFF_RS,  rs + b * 96, 96, tid);
    scopy(sm + OFF_CRD, coords, 24, tid);
    __syncthreads();

    // ---- nucleus MLP layer 1: 256 -> 81. lane = electron; warp owns 6 features.
    // X from bf16 X2 (conflict-free: bank = lane); NW1 via warp-uniform __ldg. ----
    {
        float ac[6]; int fi[6];
        #pragma unroll
        for (int c = 0; c < 6; ++c) {
            int f = warp + 16 * c; fi[c] = f;
            ac[c] = sm[OFF_NB1 + ((f < 81) ? f : 0)];
        }
        #pragma unroll 2
        for (int dp = 0; dp < 128; ++dp) {
            __nv_bfloat162 xv = asbf2(smu[OFF_X2 + dp * 32 + lane]);
            float xlo = __low2float(xv), xhi = __high2float(xv);
            #pragma unroll
            for (int c = 0; c < 6; ++c) {
                int fs = (fi[c] < 81) ? fi[c] : 0;
                ac[c] = fmaf(xlo, __ldg(nw1 + (2 * dp + 0) * 81 + fs), ac[c]);
                ac[c] = fmaf(xhi, __ldg(nw1 + (2 * dp + 1) * 81 + fs), ac[c]);
            }
        }
        #pragma unroll
        for (int c = 0; c < 6; ++c)
            if (fi[c] < 81) sm[OFF_H1T + fi[c] * 33 + lane] = ssp(ac[c]);
    }
    __syncthreads();

    // ---- nucleus layer 2: 81 -> 25 ----
    {
        int c0 = warp, c1 = warp + 16;
        float a0 = sm[OFF_NB2 + c0];
        float a1 = (c1 < 25) ? sm[OFF_NB2 + c1] : 0.0f;
        int c1s = (c1 < 25) ? c1 : 0;
        #pragma unroll 3
        for (int f = 0; f < 81; ++f) {
            float h = sm[OFF_H1T + f * 33 + lane];
            a0 = fmaf(h, sm[OFF_NW2 + f * 25 + c0], a0);
            a1 = fmaf(h, sm[OFF_NW2 + f * 25 + c1s], a1);
        }
        sm[OFF_H2T + c0 * 33 + lane] = ssp(a0);
        if (c1 < 25) sm[OFF_H2T + c1 * 33 + lane] = ssp(a1);
    }
    __syncthreads();

    // ---- nucleus layer 3: 25 -> 8 ----
    if (warp < 8) {
        int k = warp;
        float a = sm[OFF_NB3 + k];
        #pragma unroll
        for (int c = 0; c < 25; ++c)
            a = fmaf(sm[OFF_H2T + c * 33 + lane], sm[OFF_NW3 + c * 8 + k], a);
        sm[OFF_WN + lane * 8 + k] = a;
    }
    __syncthreads();

    // ---- bf_nuc + cutoff (seeds the scatter-add accumulator) ----
    if (tid < 32) {
        const int i = tid;
        float rx = sm[OFF_RS + i * 3 + 0], ry = sm[OFF_RS + i * 3 + 1], rz = sm[OFF_RS + i * 3 + 2];
        float bx = 0.f, by = 0.f, bz = 0.f, cut = 1.f;
        #pragma unroll
        for (int k = 0; k < 8; ++k) {
            float dx = rx - sm[OFF_CRD + k * 3 + 0];
            float dy = ry - sm[OFF_CRD + k * 3 + 1];
            float dz = rz - sm[OFF_CRD + k * 3 + 2];
            float dist = sqrtf(dx * dx + dy * dy + dz * dz);
            float rr = dist * 2.0f;
            float cv = (rr < 0.5f) ? rr * rr * (6.0f - 8.0f * rr + 3.0f * rr * rr) : 1.0f;
            cut *= cv;
            float wk = sm[OFF_WN + i * 8 + k];
            bx = fmaf(wk, dx, bx); by = fmaf(wk, dy, by); bz = fmaf(wk, dz, bz);
        }
        sm[OFF_BFN + i * 3 + 0] = bx;
        sm[OFF_BFN + i * 3 + 1] = by;
        sm[OFF_BFN + i * 3 + 2] = bz;
        sm[OFF_CUT + i] = cut;
    }
    __syncthreads();

    // ---- pair MLP layer 1: one thread per unordered pair, bf16 HFMA2 single pass.
    // acc[q] = bf16x2 partial sums for features (2q, 2q+1). ----
    const bool valid = (tid < 496);
    int pi, pj;
    pair_of(tid, pi, pj);

    __nv_bfloat162 acc[20];
    #pragma unroll
    for (int q = 0; q < 20; ++q) acc[q] = __floats2bfloat162_rn(0.f, 0.f);

    const uint32_t* X2 = smu + OFF_X2;

    #pragma unroll 2
    for (int dp = 0; dp < 128; ++dp) {
        __nv_bfloat162 a = asbf2(X2[dp * 32 + pi]);
        __nv_bfloat162 c = asbf2(X2[dp * 32 + pj]);
        __nv_bfloat162 pr = __hmul2(a, c);            // (p_{2dp}, p_{2dp+1})
        __nv_bfloat162 pe = __low2bfloat162(pr);      // splat even-d product
        __nv_bfloat162 po = __high2bfloat162(pr);     // splat odd-d product
        const uint4* we = reinterpret_cast<const uint4*>(smu + OFF_W1B + (2 * dp + 0) * 20);
        const uint4* wo = reinterpret_cast<const uint4*>(smu + OFF_W1B + (2 * dp + 1) * 20);
        #pragma unroll
        for (int u = 0; u < 5; ++u) {
            uint4 w = we[u];
            acc[4 * u + 0] = __hfma2(pe, asbf2(w.x), acc[4 * u + 0]);
            acc[4 * u + 1] = __hfma2(pe, asbf2(w.y), acc[4 * u + 1]);
            acc[4 * u + 2] = __hfma2(pe, asbf2(w.z), acc[4 * u + 2]);
            acc[4 * u + 3] = __hfma2(pe, asbf2(w.w), acc[4 * u + 3]);
        }
        #pragma unroll
        for (int u = 0; u < 5; ++u) {
            uint4 w = wo[u];
            acc[4 * u + 0] = __hfma2(po, asbf2(w.x), acc[4 * u + 0]);
            acc[4 * u + 1] = __hfma2(po, asbf2(w.y), acc[4 * u + 1]);
            acc[4 * u + 2] = __hfma2(po, asbf2(w.z), acc[4 * u + 2]);
            acc[4 * u + 3] = __hfma2(po, asbf2(w.w), acc[4 * u + 3]);
        }
    }

    // ---- pair layers 2/3 (fp32) ----
    float h2[6];
    #pragma unroll
    for (int c = 0; c < 6; ++c) h2[c] = sm[OFF_EB2 + c];
    #pragma unroll
    for (int q = 0; q < 20; ++q) {
        float h0 = ssp(__low2float(acc[q])  + sm[OFF_EB1 + 2 * q + 0]);
        float h1 = ssp(__high2float(acc[q]) + sm[OFF_EB1 + 2 * q + 1]);
        #pragma unroll
        for (int c = 0; c < 6; ++c) {
            h2[c] = fmaf(h0, sm[OFF_W2 + (2 * q + 0) * 6 + c], h2[c]);
            h2[c] = fmaf(h1, sm[OFF_W2 + (2 * q + 1) * 6 + c], h2[c]);
        }
    }
    float w = sm[OFF_EB3];
    #pragma unroll
    for (int c = 0; c < 6; ++c) w = fmaf(ssp(h2[c]), sm[OFF_W3 + c], w);
    if (!valid) w = 0.0f;

    // ---- scatter-add +- w * (r_i - r_j) ----
    {
        float dx = sm[OFF_RS + pi * 3 + 0] - sm[OFF_RS + pj * 3 + 0];
        float dy = sm[OFF_RS + pi * 3 + 1] - sm[OFF_RS + pj * 3 + 1];
        float dz = sm[OFF_RS + pi * 3 + 2] - sm[OFF_RS + pj * 3 + 2];
        float cx = w * dx, cy = w * dy, cz = w * dz;
        atomicAdd(&sm[OFF_BFN + pi * 3 + 0],  cx);
        atomicAdd(&sm[OFF_BFN + pi * 3 + 1],  cy);
        atomicAdd(&sm[OFF_BFN + pi * 3 + 2],  cz);
        atomicAdd(&sm[OFF_BFN + pj * 3 + 0], -cx);
        atomicAdd(&sm[OFF_BFN + pj * 3 + 1], -cy);
        atomicAdd(&sm[OFF_BFN + pj * 3 + 2], -cz);
    }
    __syncthreads();

    // ---- final output ----
    if (tid < 96) {
        int i = tid / 3;
        float s = 1e-4f * sm[OFF_CUT + i];
        out[b * 96 + tid] = fmaf(s, sm[OFF_BFN + tid], sm[OFF_RS + tid]);
    }
}

extern "C" void kernel_launch(void* const* d_in, const int* in_sizes, int n_in,
                              void* d_out, int out_size)
{
    const float* rs     = (const float*)d_in[0];
    const float* xs     = (const float*)d_in[1];
    const float* coords = (const float*)d_in[2];
    const float* ew1    = (const float*)d_in[3];
    const float* eb1    = (const float*)d_in[4];
    const float* ew2    = (const float*)d_in[5];
    const float* eb2    = (const float*)d_in[6];
    const float* ew3    = (const float*)d_in[7];
    const float* eb3    = (const float*)d_in[8];
    const float* nw1    = (const float*)d_in[9];
    const float* nb1    = (const float*)d_in[10];
    const float* nw2    = (const float*)d_in[11];
    const float* nb2    = (const float*)d_in[12];
    const float* nw3    = (const float*)d_in[13];
    const float* nb3    = (const float*)d_in[14];
    float* out = (float*)d_out;

    int B = in_sizes[0] / 96;

    cudaFuncSetAttribute(backflow_kernel,
                         cudaFuncAttributeMaxDynamicSharedMemorySize, SMEM_BYTES);
    backflow_kernel<<<B, NTHREADS, SMEM_BYTES>>>(
        rs, xs, coords, ew1, eb1, ew2, eb2, ew3, eb3,
        nw1, nb1, nw2, nb2, nw3, nb3, out);
}